// round 13
// baseline (speedup 1.0000x reference)
#include <cuda_runtime.h>
#include <cstdint>
#include <math.h>

// ---------------- problem constants ----------------
#define NTOK    32768
#define NEXP    16
#define LINP    1792
#define KC      32
#define NCHUNK  56
#define TPB     128
#define TOKBLK  64
#define NBLK    (NTOK / TOKBLK)   // 512

#define IDX_OFF (NTOK * NEXP)
#define G1_OFF  (IDX_OFF + NTOK * 2)

// smem: Xs[2][64][36] f32 = 18432B ; Wf[2][2048] f32 = 16384B
#define SM_X       0
#define SM_W       18432
#define SMEM_BYTES 34816

// W fragments: [chunk][split hi/lo][kstep 4][ntile 4][lane 32][2]
__device__ __align__(16) float g_wfrag[NCHUNK * 2048];
__device__ float2 g_bias[NEXP];

// ---------------- helpers ----------------
__device__ __forceinline__ uint32_t tf32u(float x) {
    uint32_t u;
    asm("cvt.rn.tf32.f32 %0, %1;" : "=r"(u) : "f"(x));
    return u;
}
__device__ __forceinline__ float softplus_f(float x) {
    return fmaxf(x, 0.f) + log1pf(expf(-fabsf(x)));
}
__device__ __forceinline__ uint32_t s2u(const void* p) {
    uint32_t a;
    asm("{ .reg .u64 t; cvta.to.shared.u64 t, %1; cvt.u32.u64 %0, t; }"
        : "=r"(a) : "l"(p));
    return a;
}
__device__ __forceinline__ void cpa16(uint32_t d, const void* s) {
    asm volatile("cp.async.cg.shared.global [%0], [%1], 16;" :: "r"(d), "l"(s));
}
#define CP_COMMIT() asm volatile("cp.async.commit_group;" ::: "memory")
#define CP_WAIT1()  asm volatile("cp.async.wait_group 1;" ::: "memory")
#define CP_WAIT0()  asm volatile("cp.async.wait_group 0;" ::: "memory")

__device__ __forceinline__ void sts128(uint32_t a, float4 v) {
    asm volatile("st.shared.v4.f32 [%0], {%1,%2,%3,%4};"
                 :: "r"(a), "f"(v.x), "f"(v.y), "f"(v.z), "f"(v.w));
}
__device__ __forceinline__ void lds64(uint32_t a, uint32_t& r0, uint32_t& r1) {
    asm volatile("ld.shared.v2.b32 {%0,%1}, [%2];" : "=r"(r0), "=r"(r1) : "r"(a));
}
__device__ __forceinline__ void mma1688(float* d, const uint32_t* a,
                                        const uint32_t* b) {
    asm volatile(
        "mma.sync.aligned.m16n8k8.row.col.f32.tf32.tf32.f32 "
        "{%0,%1,%2,%3}, {%4,%5,%6,%7}, {%8,%9}, {%0,%1,%2,%3};"
        : "+f"(d[0]), "+f"(d[1]), "+f"(d[2]), "+f"(d[3])
        : "r"(a[0]), "r"(a[1]), "r"(a[2]), "r"(a[3]), "r"(b[0]), "r"(b[1]));
}

// ---------------- prep: W -> tf32 hi/lo fragments in per-lane order ----------------
__global__ void prep_kernel(const float* __restrict__ w_route,
                            const float* __restrict__ b_route,
                            const float* __restrict__ w_noise,
                            const float* __restrict__ b_noise,
                            const float* __restrict__ city_emb,
                            const int*   __restrict__ city_index)
{
    int idx = blockIdx.x * blockDim.x + threadIdx.x;
    if (idx < NCHUNK * 2048) {
        int c  = idx >> 11;
        int r  = idx & 2047;
        int s  = r >> 10;            // 0 = hi, 1 = lo
        int r2 = r & 1023;
        int ks = r2 >> 8;
        int r3 = r2 & 255;
        int nt = r3 >> 6;
        int r4 = r3 & 63;
        int l  = r4 >> 1;
        int j  = r4 & 1;
        int kl = ks * 8 + (l & 3) + 4 * j;   // b_j: k = l%4 (+4 for j=1)
        int n  = nt * 8 + (l >> 2);          // col = l/4
        int kk = c * 32 + kl;
        int g  = kk + (kk >= 1024 ? 32 : 0); // skip city rows [1024,1056)
        float wv = (n < 16) ? w_route[g * 16 + n] : w_noise[g * 16 + (n - 16)];
        float hi = __uint_as_float(tf32u(wv));
        g_wfrag[idx] = (s == 0) ? hi : __uint_as_float(tf32u(wv - hi));
    }
    if (idx < NEXP) {
        int ci = city_index[0];
        float br = b_route[idx], bn = b_noise[idx];
        #pragma unroll
        for (int j = 0; j < 32; j++) {
            float cv = city_emb[ci * 32 + j];
            br = fmaf(cv, w_route[(1024 + j) * 16 + idx], br);
            bn = fmaf(cv, w_noise[(1024 + j) * 16 + idx], bn);
        }
        g_bias[idx] = make_float2(br, bn);
    }
}

// ---------------- main kernel ----------------
__global__ __launch_bounds__(TPB, 4)
void router_main(const float* __restrict__ mh,
                 const float* __restrict__ dt,
                 const float* __restrict__ dd,
                 const float* __restrict__ drg,
                 const float* __restrict__ dent,
                 const float* __restrict__ eps,
                 float* __restrict__ out,
                 int out_size)
{
    extern __shared__ __align__(16) char smc[];
    const uint32_t sb = s2u(smc);
    float* Xsf = reinterpret_cast<float*>(smc);

    const int tid  = threadIdx.x;
    const int lane = tid & 31;
    const int wid  = tid >> 5;
    const int tb   = blockIdx.x * TOKBLK;

    // D accumulators: [ntile 4][4] ; warp covers tokens 16*wid..16*wid+15
    float d[4][4];
    #pragma unroll
    for (int nt = 0; nt < 4; nt++)
        #pragma unroll
        for (int j = 0; j < 4; j++) d[nt][j] = 0.f;

    // loader: lf = feature quad (0..7), lt = token base (0..15)
    const int lf = tid & 7;
    const int lt = tid >> 3;

    float4 xr[4];

    auto prefetchX = [&](int c) {
        const float* src; int col, stride;
        if (c < 32)      { src = mh;   col = c * 32;        stride = 1024; }
        else if (c < 40) { src = dt;   col = (c - 32) * 32; stride = 256;  }
        else if (c < 48) { src = dd;   col = (c - 40) * 32; stride = 256;  }
        else if (c < 52) { src = drg;  col = (c - 48) * 32; stride = 128;  }
        else             { src = dent; col = (c - 52) * 32; stride = 128;  }
        const float* g = src + (size_t)(tb + lt) * stride + col + 4 * lf;
        #pragma unroll
        for (int q = 0; q < 4; q++)
            xr[q] = *reinterpret_cast<const float4*>(g + (size_t)(16 * q) * stride);
    };
    // X tile: [token][36] fp32, raw (conversion happens at fragment load)
    auto storeX = [&](int b) {
        const uint32_t xb = sb + SM_X + (uint32_t)b * 9216;
        #pragma unroll
        for (int q = 0; q < 4; q++) {
            const int tok = lt + 16 * q;
            sts128(xb + (uint32_t)(tok * 144 + 16 * lf), xr[q]);
        }
    };
    auto issueW = [&](int c) {
        if (c >= NCHUNK) return;
        const char* gs = (const char*)(g_wfrag + (size_t)c * 2048);
        const uint32_t dst = sb + SM_W + (uint32_t)(c & 1) * 8192 + tid * 64;
        #pragma unroll
        for (int k = 0; k < 4; k++) cpa16(dst + k * 16, gs + tid * 64 + k * 16);
        CP_COMMIT();
    };

    prefetchX(0);
    issueW(0);

    const int fr = lane >> 2;     // fragment row within m16
    const int fc = lane & 3;      // fragment col within k8
    const int tok0 = 16 * wid + fr;

    for (int c = 0; c < NCHUNK; c++) {
        const int b = c & 1;
        __syncthreads();                 // compute(c-1) done: buffers reusable
        storeX(b);
        if (c + 1 < NCHUNK) {
            prefetchX(c + 1);
            issueW(c + 1);
            CP_WAIT1();                  // W(c) landed
        } else {
            CP_WAIT0();
        }
        __syncthreads();                 // X(c) stores + W(c) visible

        const float* X = Xsf + b * 2304;                 // [64][36]
        const uint32_t wbase = sb + SM_W + (uint32_t)b * 8192;

        #pragma unroll
        for (int ks = 0; ks < 4; ks++) {
            // B fragments (conflict-free LDS.64, per-lane order)
            uint32_t bh[4][2], bl[4][2];
            #pragma unroll
            for (int nt = 0; nt < 4; nt++) {
                lds64(wbase + (uint32_t)(((0 * 4 + ks) * 4 + nt) * 256 + 8 * lane),
                      bh[nt][0], bh[nt][1]);
                lds64(wbase + (uint32_t)(((1 * 4 + ks) * 4 + nt) * 256 + 8 * lane),
                      bl[nt][0], bl[nt][1]);
            }
            const float x0 = X[tok0 * 36 + ks * 8 + fc];
            const float x1 = X[(tok0 + 8) * 36 + ks * 8 + fc];
            const float x2 = X[tok0 * 36 + ks * 8 + fc + 4];
            const float x3 = X[(tok0 + 8) * 36 + ks * 8 + fc + 4];
            uint32_t ah[4], al[4];
            ah[0] = tf32u(x0); ah[1] = tf32u(x1);
            ah[2] = tf32u(x2); ah[3] = tf32u(x3);
            al[0] = tf32u(x0 - __uint_as_float(ah[0]));
            al[1] = tf32u(x1 - __uint_as_float(ah[1]));
            al[2] = tf32u(x2 - __uint_as_float(ah[2]));
            al[3] = tf32u(x3 - __uint_as_float(ah[3]));
            #pragma unroll
            for (int nt = 0; nt < 4; nt++) {
                mma1688(d[nt], ah, bh[nt]);
                mma1688(d[nt], al, bh[nt]);
                mma1688(d[nt], ah, bl[nt]);
            }
        }
    }

    // ---------------- write D fragments to smem [64][33] ----------------
    __syncthreads();
    float* red = Xsf;
    #pragma unroll
    for (int nt = 0; nt < 4; nt++) {
        const int n = 8 * nt + 2 * fc;
        red[tok0 * 33 + n]           = d[nt][0];
        red[tok0 * 33 + n + 1]       = d[nt][1];
        red[(tok0 + 8) * 33 + n]     = d[nt][2];
        red[(tok0 + 8) * 33 + n + 1] = d[nt][3];
    }
    __syncthreads();

    // ---------------- per-token epilogue (64 threads, 1 token each) ----------------
    if (tid < TOKBLK) {
        const int t = tb + tid;
        float nz[16];
        {
            float4 ev[4];
            const float4* ep = reinterpret_cast<const float4*>(eps + (size_t)t * 16);
            ev[0] = ep[0]; ev[1] = ep[1]; ev[2] = ep[2]; ev[3] = ep[3];
            const float* ef = reinterpret_cast<const float*>(ev);
            #pragma unroll
            for (int e = 0; e < 16; e++) {
                float2 bso = g_bias[e];
                float route = red[tid * 33 + e] + bso.x;
                float noise = red[tid * 33 + 16 + e] + bso.y;
                nz[e] = route + ef[e] * softplus_f(noise);
            }
        }

        float m = nz[0];
        #pragma unroll
        for (int e = 1; e < 16; e++) m = fmaxf(m, nz[e]);
        float ex[16], ssum = 0.f;
        #pragma unroll
        for (int e = 0; e < 16; e++) { ex[e] = expf(nz[e] - m); ssum += ex[e]; }
        float inv = 1.f / ssum;

        int i1 = 0; float v1 = nz[0];
        #pragma unroll
        for (int e = 1; e < 16; e++) if (nz[e] > v1) { v1 = nz[e]; i1 = e; }
        int i2 = -1; float v2 = -INFINITY;
        #pragma unroll
        for (int e = 0; e < 16; e++) if (e != i1 && nz[e] > v2) { v2 = nz[e]; i2 = e; }

        float t2 = expf(v2 - v1);
        float r1 = 1.f / (1.f + t2);
        float r2 = t2 * r1;

        {
            float ro[16];
            #pragma unroll
            for (int e = 0; e < 16; e++)
                ro[e] = (e == i1) ? r1 : ((e == i2) ? r2 : 0.f);
            float4* op = reinterpret_cast<float4*>(out + (size_t)t * 16);
            op[0] = make_float4(ro[0],  ro[1],  ro[2],  ro[3]);
            op[1] = make_float4(ro[4],  ro[5],  ro[6],  ro[7]);
            op[2] = make_float4(ro[8],  ro[9],  ro[10], ro[11]);
            op[3] = make_float4(ro[12], ro[13], ro[14], ro[15]);
        }
        if (out_size >= IDX_OFF + NTOK * 2) {
            float2* ip = reinterpret_cast<float2*>(out + IDX_OFF + (size_t)t * 2);
            ip[0] = make_float2((float)i1, (float)i2);
        }
        if (out_size >= G1_OFF + NTOK * NEXP) {
            float g[16];
            #pragma unroll
            for (int e = 0; e < 16; e++) g[e] = ex[e] * inv;
            float4* gp = reinterpret_cast<float4*>(out + G1_OFF + (size_t)t * 16);
            gp[0] = make_float4(g[0],  g[1],  g[2],  g[3]);
            gp[1] = make_float4(g[4],  g[5],  g[6],  g[7]);
            gp[2] = make_float4(g[8],  g[9],  g[10], g[11]);
            gp[3] = make_float4(g[12], g[13], g[14], g[15]);
        }
    }
}

// ---------------- launch ----------------
extern "C" void kernel_launch(void* const* d_in, const int* in_sizes, int n_in,
                              void* d_out, int out_size)
{
    const float* mh      = (const float*)d_in[0];
    const float* dt      = (const float*)d_in[1];
    const float* dd      = (const float*)d_in[2];
    const float* drg     = (const float*)d_in[3];
    const float* dent    = (const float*)d_in[4];
    const float* city    = (const float*)d_in[5];
    const float* w_route = (const float*)d_in[6];
    const float* b_route = (const float*)d_in[7];
    const float* w_noise = (const float*)d_in[8];
    const float* b_noise = (const float*)d_in[9];
    const float* eps     = (const float*)d_in[10];
    const int*   ci      = (const int*)d_in[11];

    cudaFuncSetAttribute(router_main,
                         cudaFuncAttributeMaxDynamicSharedMemorySize, SMEM_BYTES);

    prep_kernel<<<(NCHUNK * 2048 + 255) / 256, 256>>>(w_route, b_route,
                                                      w_noise, b_noise, city, ci);
    router_main<<<NBLK, TPB, SMEM_BYTES>>>(mh, dt, dd, drg, dent, eps,
                                           (float*)d_out, out_size);
}

// round 14
// speedup vs baseline: 1.1752x; 1.1752x over previous
#include <cuda_runtime.h>
#include <cstdint>
#include <math.h>

// ---------------- problem constants ----------------
#define NTOK    32768
#define NEXP    16
#define LINP    1792
#define KC      64
#define NCHUNK  28
#define TPB     128
#define TOKBLK  128
#define NBLK    (NTOK / TOKBLK)   // 256

#define IDX_OFF (NTOK * NEXP)
#define G1_OFF  (IDX_OFF + NTOK * 2)

// smem: Xs[2][128][68] f32 = 69632B ; Wf[2][4096] f32 = 32768B
#define SM_X       0
#define SM_W       69632
#define SMEM_BYTES 102400

// W fragments: [chunk][split hi/lo][kstep 8][ntile 4][lane 32][2]
__device__ __align__(16) float g_wfrag[NCHUNK * 4096];
__device__ float2 g_bias[NEXP];

// ---------------- helpers ----------------
__device__ __forceinline__ uint32_t tf32u(float x) {
    uint32_t u;
    asm("cvt.rn.tf32.f32 %0, %1;" : "=r"(u) : "f"(x));
    return u;
}
__device__ __forceinline__ float softplus_f(float x) {
    return fmaxf(x, 0.f) + log1pf(expf(-fabsf(x)));
}
__device__ __forceinline__ uint32_t s2u(const void* p) {
    uint32_t a;
    asm("{ .reg .u64 t; cvta.to.shared.u64 t, %1; cvt.u32.u64 %0, t; }"
        : "=r"(a) : "l"(p));
    return a;
}
__device__ __forceinline__ void cpa16(uint32_t d, const void* s) {
    asm volatile("cp.async.cg.shared.global [%0], [%1], 16;" :: "r"(d), "l"(s));
}
#define CP_COMMIT() asm volatile("cp.async.commit_group;" ::: "memory")
#define CP_WAIT0()  asm volatile("cp.async.wait_group 0;" ::: "memory")

__device__ __forceinline__ void sts128(uint32_t a, float4 v) {
    asm volatile("st.shared.v4.f32 [%0], {%1,%2,%3,%4};"
                 :: "r"(a), "f"(v.x), "f"(v.y), "f"(v.z), "f"(v.w));
}
__device__ __forceinline__ void lds64(uint32_t a, uint32_t& r0, uint32_t& r1) {
    asm volatile("ld.shared.v2.b32 {%0,%1}, [%2];" : "=r"(r0), "=r"(r1) : "r"(a));
}
__device__ __forceinline__ void mma1688(float* d, const uint32_t* a,
                                        const uint32_t* b) {
    asm volatile(
        "mma.sync.aligned.m16n8k8.row.col.f32.tf32.tf32.f32 "
        "{%0,%1,%2,%3}, {%4,%5,%6,%7}, {%8,%9}, {%0,%1,%2,%3};"
        : "+f"(d[0]), "+f"(d[1]), "+f"(d[2]), "+f"(d[3])
        : "r"(a[0]), "r"(a[1]), "r"(a[2]), "r"(a[3]), "r"(b[0]), "r"(b[1]));
}

// ---------------- prep: W -> tf32 hi/lo fragments in per-lane order ----------------
__global__ void prep_kernel(const float* __restrict__ w_route,
                            const float* __restrict__ b_route,
                            const float* __restrict__ w_noise,
                            const float* __restrict__ b_noise,
                            const float* __restrict__ city_emb,
                            const int*   __restrict__ city_index)
{
    int idx = blockIdx.x * blockDim.x + threadIdx.x;
    if (idx < NCHUNK * 4096) {
        int c  = idx >> 12;
        int r  = idx & 4095;
        int s  = r >> 11;            // 0 = hi, 1 = lo
        int r2 = r & 2047;
        int ks = r2 >> 8;            // 0..7
        int r3 = r2 & 255;
        int nt = r3 >> 6;
        int r4 = r3 & 63;
        int l  = r4 >> 1;
        int j  = r4 & 1;
        int kl = ks * 8 + (l & 3) + 4 * j;   // b_j: k = l%4 (+4 for j=1)
        int n  = nt * 8 + (l >> 2);          // col = l/4
        int kk = c * 64 + kl;
        int g  = kk + (kk >= 1024 ? 32 : 0); // skip city rows [1024,1056)
        float wv = (n < 16) ? w_route[g * 16 + n] : w_noise[g * 16 + (n - 16)];
        float hi = __uint_as_float(tf32u(wv));
        g_wfrag[idx] = (s == 0) ? hi : __uint_as_float(tf32u(wv - hi));
    }
    if (idx < NEXP) {
        int ci = city_index[0];
        float br = b_route[idx], bn = b_noise[idx];
        #pragma unroll
        for (int j = 0; j < 32; j++) {
            float cv = city_emb[ci * 32 + j];
            br = fmaf(cv, w_route[(1024 + j) * 16 + idx], br);
            bn = fmaf(cv, w_noise[(1024 + j) * 16 + idx], bn);
        }
        g_bias[idx] = make_float2(br, bn);
    }
}

// ---------------- main kernel ----------------
__global__ __launch_bounds__(TPB, 2)
void router_main(const float* __restrict__ mh,
                 const float* __restrict__ dt,
                 const float* __restrict__ dd,
                 const float* __restrict__ drg,
                 const float* __restrict__ dent,
                 const float* __restrict__ eps,
                 float* __restrict__ out,
                 int out_size)
{
    extern __shared__ __align__(16) char smc[];
    const uint32_t sb = s2u(smc);
    float* Xsf = reinterpret_cast<float*>(smc);

    const int tid  = threadIdx.x;
    const int lane = tid & 31;
    const int wid  = tid >> 5;
    const int tb   = blockIdx.x * TOKBLK;

    // D accumulators: [mtile 2][ntile 4][4]
    float d[2][4][4];
    #pragma unroll
    for (int mt = 0; mt < 2; mt++)
        #pragma unroll
        for (int nt = 0; nt < 4; nt++)
            #pragma unroll
            for (int j = 0; j < 4; j++) d[mt][nt][j] = 0.f;

    // loader: lf = feature quad (0..15), lt = token base (0..7), 16 rounds
    const int lf = tid & 15;
    const int lt = tid >> 4;

    float4 xr[16];

    auto prefetchX = [&](int c) {
        if (c >= NCHUNK) return;
        const float* src; int col, stride;
        if (c < 16)      { src = mh;   col = c * 64;        stride = 1024; }
        else if (c < 20) { src = dt;   col = (c - 16) * 64; stride = 256;  }
        else if (c < 24) { src = dd;   col = (c - 20) * 64; stride = 256;  }
        else if (c < 26) { src = drg;  col = (c - 24) * 64; stride = 128;  }
        else             { src = dent; col = (c - 26) * 64; stride = 128;  }
        const float* g = src + (size_t)(tb + lt) * stride + col + 4 * lf;
        #pragma unroll
        for (int q = 0; q < 16; q++)
            xr[q] = *reinterpret_cast<const float4*>(g + (size_t)(8 * q) * stride);
    };
    // X tile: [token][68] fp32 raw
    auto storeX = [&](int b) {
        const uint32_t xb = sb + SM_X + (uint32_t)b * 34816;
        #pragma unroll
        for (int q = 0; q < 16; q++) {
            const int tok = lt + 8 * q;
            sts128(xb + (uint32_t)(tok * 272 + 16 * lf), xr[q]);
        }
    };
    auto issueW = [&](int c) {
        if (c >= NCHUNK) return;
        const char* gs = (const char*)(g_wfrag + (size_t)c * 4096);
        const uint32_t dst = sb + SM_W + (uint32_t)(c & 1) * 16384 + tid * 128;
        #pragma unroll
        for (int k = 0; k < 8; k++) cpa16(dst + k * 16, gs + tid * 128 + k * 16);
        CP_COMMIT();
    };

    // ---- prologue: X(0) staged, W(0)+W(1) issued, W all waited ----
    prefetchX(0);
    storeX(0);
    issueW(0);
    issueW(1);
    CP_WAIT0();          // both W(0) and W(1) landed (simple; prologue only)
    __syncthreads();

    const int fr = lane >> 2;     // fragment row within m16
    const int fc = lane & 3;      // fragment col within k8

    for (int c = 0; c < NCHUNK; c++) {
        const int b = c & 1;
        const float* X = Xsf + b * 8704;                  // [128][68]
        const uint32_t wbase = sb + SM_W + (uint32_t)b * 16384;

        prefetchX(c + 1);

        #pragma unroll
        for (int ks = 0; ks < 8; ks++) {
            uint32_t bh[4][2], bl[4][2];
            #pragma unroll
            for (int nt = 0; nt < 4; nt++) {
                lds64(wbase + (uint32_t)(((0 * 8 + ks) * 4 + nt) * 256 + 8 * lane),
                      bh[nt][0], bh[nt][1]);
                lds64(wbase + (uint32_t)(((1 * 8 + ks) * 4 + nt) * 256 + 8 * lane),
                      bl[nt][0], bl[nt][1]);
            }
            #pragma unroll
            for (int mt = 0; mt < 2; mt++) {
                const int tok0 = 32 * wid + 16 * mt + fr;
                const float x0 = X[tok0 * 68 + ks * 8 + fc];
                const float x1 = X[(tok0 + 8) * 68 + ks * 8 + fc];
                const float x2 = X[tok0 * 68 + ks * 8 + fc + 4];
                const float x3 = X[(tok0 + 8) * 68 + ks * 8 + fc + 4];
                uint32_t ah[4], al[4];
                ah[0] = tf32u(x0); ah[1] = tf32u(x1);
                ah[2] = tf32u(x2); ah[3] = tf32u(x3);
                al[0] = tf32u(x0 - __uint_as_float(ah[0]));
                al[1] = tf32u(x1 - __uint_as_float(ah[1]));
                al[2] = tf32u(x2 - __uint_as_float(ah[2]));
                al[3] = tf32u(x3 - __uint_as_float(ah[3]));
                #pragma unroll
                for (int nt = 0; nt < 4; nt++) {
                    mma1688(d[mt][nt], ah, bh[nt]);
                    mma1688(d[mt][nt], al, bh[nt]);
                    mma1688(d[mt][nt], ah, bl[nt]);
                }
            }
            if (ks == 3 && c + 1 < NCHUNK) storeX(b ^ 1);   // mid-compute store
        }

        if (c + 1 < NCHUNK) CP_WAIT0();   // W(c+1) landed (only group in flight)
        __syncthreads();                  // X(c+1) + W(c+1) visible; bufs b free
        issueW(c + 2);                    // slot (c+2)&1 = b, freed by barrier
    }

    // ---------------- write D fragments to smem [128][33] ----------------
    float* red = Xsf;
    #pragma unroll
    for (int mt = 0; mt < 2; mt++) {
        const int tok = 32 * wid + 16 * mt + fr;
        #pragma unroll
        for (int nt = 0; nt < 4; nt++) {
            const int n = 8 * nt + 2 * fc;
            red[tok * 33 + n]           = d[mt][nt][0];
            red[tok * 33 + n + 1]       = d[mt][nt][1];
            red[(tok + 8) * 33 + n]     = d[mt][nt][2];
            red[(tok + 8) * 33 + n + 1] = d[mt][nt][3];
        }
    }
    __syncthreads();

    // ---------------- per-token epilogue (128 threads, 1 token each) ----------------
    {
        const int t = tb + tid;
        float nz[16];
        {
            float4 ev[4];
            const float4* ep = reinterpret_cast<const float4*>(eps + (size_t)t * 16);
            ev[0] = ep[0]; ev[1] = ep[1]; ev[2] = ep[2]; ev[3] = ep[3];
            const float* ef = reinterpret_cast<const float*>(ev);
            #pragma unroll
            for (int e = 0; e < 16; e++) {
                float2 bso = g_bias[e];
                float route = red[tid * 33 + e] + bso.x;
                float noise = red[tid * 33 + 16 + e] + bso.y;
                nz[e] = route + ef[e] * softplus_f(noise);
            }
        }

        float m = nz[0];
        #pragma unroll
        for (int e = 1; e < 16; e++) m = fmaxf(m, nz[e]);
        float ex[16], ssum = 0.f;
        #pragma unroll
        for (int e = 0; e < 16; e++) { ex[e] = expf(nz[e] - m); ssum += ex[e]; }
        float inv = 1.f / ssum;

        int i1 = 0; float v1 = nz[0];
        #pragma unroll
        for (int e = 1; e < 16; e++) if (nz[e] > v1) { v1 = nz[e]; i1 = e; }
        int i2 = -1; float v2 = -INFINITY;
        #pragma unroll
        for (int e = 0; e < 16; e++) if (e != i1 && nz[e] > v2) { v2 = nz[e]; i2 = e; }

        float t2 = expf(v2 - v1);
        float r1 = 1.f / (1.f + t2);
        float r2 = t2 * r1;

        {
            float ro[16];
            #pragma unroll
            for (int e = 0; e < 16; e++)
                ro[e] = (e == i1) ? r1 : ((e == i2) ? r2 : 0.f);
            float4* op = reinterpret_cast<float4*>(out + (size_t)t * 16);
            op[0] = make_float4(ro[0],  ro[1],  ro[2],  ro[3]);
            op[1] = make_float4(ro[4],  ro[5],  ro[6],  ro[7]);
            op[2] = make_float4(ro[8],  ro[9],  ro[10], ro[11]);
            op[3] = make_float4(ro[12], ro[13], ro[14], ro[15]);
        }
        if (out_size >= IDX_OFF + NTOK * 2) {
            float2* ip = reinterpret_cast<float2*>(out + IDX_OFF + (size_t)t * 2);
            ip[0] = make_float2((float)i1, (float)i2);
        }
        if (out_size >= G1_OFF + NTOK * NEXP) {
            float g[16];
            #pragma unroll
            for (int e = 0; e < 16; e++) g[e] = ex[e] * inv;
            float4* gp = reinterpret_cast<float4*>(out + G1_OFF + (size_t)t * 16);
            gp[0] = make_float4(g[0],  g[1],  g[2],  g[3]);
            gp[1] = make_float4(g[4],  g[5],  g[6],  g[7]);
            gp[2] = make_float4(g[8],  g[9],  g[10], g[11]);
            gp[3] = make_float4(g[12], g[13], g[14], g[15]);
        }
    }
}

// ---------------- launch ----------------
extern "C" void kernel_launch(void* const* d_in, const int* in_sizes, int n_in,
                              void* d_out, int out_size)
{
    const float* mh      = (const float*)d_in[0];
    const float* dt      = (const float*)d_in[1];
    const float* dd      = (const float*)d_in[2];
    const float* drg     = (const float*)d_in[3];
    const float* dent    = (const float*)d_in[4];
    const float* city    = (const float*)d_in[5];
    const float* w_route = (const float*)d_in[6];
    const float* b_route = (const float*)d_in[7];
    const float* w_noise = (const float*)d_in[8];
    const float* b_noise = (const float*)d_in[9];
    const float* eps     = (const float*)d_in[10];
    const int*   ci      = (const int*)d_in[11];

    cudaFuncSetAttribute(router_main,
                         cudaFuncAttributeMaxDynamicSharedMemorySize, SMEM_BYTES);

    prep_kernel<<<(NCHUNK * 4096 + 255) / 256, 256>>>(w_route, b_route,
                                                      w_noise, b_noise, city, ci);
    router_main<<<NBLK, TPB, SMEM_BYTES>>>(mh, dt, dd, drg, dent, eps,
                                           (float*)d_out, out_size);
}

// round 16
// speedup vs baseline: 2.2636x; 1.9262x over previous
#include <cuda_runtime.h>
#include <cstdint>
#include <math.h>

// ---------------- problem constants ----------------
#define NTOK    32768
#define NEXP    16
#define LINP    1792
#define KC      32
#define NCHUNK  56
#define TPB     128
#define TOKBLK  128
#define NBLK    (NTOK / TOKBLK)   // 256

#define IDX_OFF (NTOK * NEXP)
#define G1_OFF  (IDX_OFF + NTOK * 2)

// smem: Xs[2][128][36] f32 = 36864B ; Wf[2][1024] u32 = 8192B
#define SM_X       0
#define SM_W       36864
#define SMEM_BYTES 45056

// W fragments (bf16x2): [chunk][split hi/lo][kstep 2][ntile 4][lane 32][reg 2]
__device__ __align__(16) uint32_t g_wfrag[NCHUNK * 1024];
__device__ float2 g_bias[NEXP];

// ---------------- helpers ----------------
__device__ __forceinline__ float softplus_f(float x) {
    return fmaxf(x, 0.f) + log1pf(expf(-fabsf(x)));
}
__device__ __forceinline__ uint32_t s2u(const void* p) {
    uint32_t a;
    asm("{ .reg .u64 t; cvta.to.shared.u64 t, %1; cvt.u32.u64 %0, t; }"
        : "=r"(a) : "l"(p));
    return a;
}
__device__ __forceinline__ void cpa16(uint32_t d, const void* s) {
    asm volatile("cp.async.cg.shared.global [%0], [%1], 16;" :: "r"(d), "l"(s));
}
#define CP_COMMIT() asm volatile("cp.async.commit_group;" ::: "memory")
#define CP_WAIT1()  asm volatile("cp.async.wait_group 1;" ::: "memory")
#define CP_WAIT0()  asm volatile("cp.async.wait_group 0;" ::: "memory")

__device__ __forceinline__ void sts128(uint32_t a, float4 v) {
    asm volatile("st.shared.v4.f32 [%0], {%1,%2,%3,%4};"
                 :: "r"(a), "f"(v.x), "f"(v.y), "f"(v.z), "f"(v.w));
}
__device__ __forceinline__ void lds64u(uint32_t a, uint32_t& r0, uint32_t& r1) {
    asm volatile("ld.shared.v2.b32 {%0,%1}, [%2];" : "=r"(r0), "=r"(r1) : "r"(a));
}
__device__ __forceinline__ void lds64f(uint32_t a, float& r0, float& r1) {
    asm volatile("ld.shared.v2.f32 {%0,%1}, [%2];" : "=f"(r0), "=f"(r1) : "r"(a));
}
// pack truncated-bf16 of (x0 -> low16, x1 -> high16)
__device__ __forceinline__ uint32_t prmt_hi(float x0, float x1) {
    uint32_t r;
    asm("prmt.b32 %0, %1, %2, 0x7632;"
        : "=r"(r) : "r"(__float_as_uint(x0)), "r"(__float_as_uint(x1)));
    return r;
}
__device__ __forceinline__ float trunc_bf(float x) {
    return __uint_as_float(__float_as_uint(x) & 0xFFFF0000u);
}
// rn-bf16x2: x0 -> low16, x1 -> high16
__device__ __forceinline__ uint32_t cvt_bf16x2(float x0, float x1) {
    uint32_t r;
    asm("cvt.rn.bf16x2.f32 %0, %1, %2;" : "=r"(r) : "f"(x1), "f"(x0));
    return r;
}
__device__ __forceinline__ void mma16816(float* d, const uint32_t* a,
                                         const uint32_t* b) {
    asm volatile(
        "mma.sync.aligned.m16n8k16.row.col.f32.bf16.bf16.f32 "
        "{%0,%1,%2,%3}, {%4,%5,%6,%7}, {%8,%9}, {%0,%1,%2,%3};"
        : "+f"(d[0]), "+f"(d[1]), "+f"(d[2]), "+f"(d[3])
        : "r"(a[0]), "r"(a[1]), "r"(a[2]), "r"(a[3]), "r"(b[0]), "r"(b[1]));
}

// ---------------- prep: W -> bf16 hi/lo m16n8k16 B-fragments ----------------
__global__ void prep_kernel(const float* __restrict__ w_route,
                            const float* __restrict__ b_route,
                            const float* __restrict__ w_noise,
                            const float* __restrict__ b_noise,
                            const float* __restrict__ city_emb,
                            const int*   __restrict__ city_index)
{
    int idx = blockIdx.x * blockDim.x + threadIdx.x;
    if (idx < NCHUNK * 1024) {
        int c  = idx >> 10;
        int r  = idx & 1023;
        int s  = r >> 9;             // 0 = hi, 1 = lo
        int r2 = r & 511;
        int ks = r2 >> 8;            // 0..1
        int r3 = r2 & 255;
        int nt = r3 >> 6;
        int r4 = r3 & 63;
        int l  = r4 >> 1;
        int j  = r4 & 1;             // B reg index
        int k0 = ks * 16 + 2 * (l & 3) + 8 * j;
        int n  = nt * 8 + (l >> 2);
        uint32_t halves[2];
        #pragma unroll
        for (int q = 0; q < 2; q++) {
            int kk = c * 32 + k0 + q;
            int g  = kk + (kk >= 1024 ? 32 : 0);   // skip city rows
            float wv = (n < 16) ? w_route[g * 16 + n]
                                : w_noise[g * 16 + (n - 16)];
            if (s == 0) {
                halves[q] = __float_as_uint(wv) >> 16;           // trunc hi
            } else {
                float lo = wv - trunc_bf(wv);
                unsigned short p;
                asm("cvt.rn.bf16.f32 %0, %1;" : "=h"(p) : "f"(lo));
                halves[q] = (uint32_t)p;
            }
        }
        g_wfrag[idx] = halves[0] | (halves[1] << 16);
    }
    if (idx < NEXP) {
        int ci = city_index[0];
        float br = b_route[idx], bn = b_noise[idx];
        #pragma unroll
        for (int j = 0; j < 32; j++) {
            float cv = city_emb[ci * 32 + j];
            br = fmaf(cv, w_route[(1024 + j) * 16 + idx], br);
            bn = fmaf(cv, w_noise[(1024 + j) * 16 + idx], bn);
        }
        g_bias[idx] = make_float2(br, bn);
    }
}

// ---------------- main kernel ----------------
__global__ __launch_bounds__(TPB, 2)
void router_main(const float* __restrict__ mh,
                 const float* __restrict__ dt,
                 const float* __restrict__ dd,
                 const float* __restrict__ drg,
                 const float* __restrict__ dent,
                 const float* __restrict__ eps,
                 float* __restrict__ out,
                 int out_size)
{
    extern __shared__ __align__(16) char smc[];
    const uint32_t sb = s2u(smc);
    float* Xsf = reinterpret_cast<float*>(smc);

    const int tid  = threadIdx.x;
    const int lane = tid & 31;
    const int wid  = tid >> 5;
    const int tb   = blockIdx.x * TOKBLK;

    // D accumulators: [mtile 2][ntile 4][4]
    float d[2][4][4];
    #pragma unroll
    for (int mt = 0; mt < 2; mt++)
        #pragma unroll
        for (int nt = 0; nt < 4; nt++)
            #pragma unroll
            for (int j = 0; j < 4; j++) d[mt][nt][j] = 0.f;

    // loader: lf = feature quad (0..7), lt = token base (0..15)
    const int lf = tid & 7;
    const int lt = tid >> 3;

    float4 xr[8];

    auto prefetchX = [&](int c) {
        const float* src; int col, stride;
        if (c < 32)      { src = mh;   col = c * 32;        stride = 1024; }
        else if (c < 40) { src = dt;   col = (c - 32) * 32; stride = 256;  }
        else if (c < 48) { src = dd;   col = (c - 40) * 32; stride = 256;  }
        else if (c < 52) { src = drg;  col = (c - 48) * 32; stride = 128;  }
        else             { src = dent; col = (c - 52) * 32; stride = 128;  }
        const float* g = src + (size_t)(tb + lt) * stride + col + 4 * lf;
        #pragma unroll
        for (int q = 0; q < 8; q++)
            xr[q] = *reinterpret_cast<const float4*>(g + (size_t)(16 * q) * stride);
    };
    // X tile: [token][36] fp32, raw
    auto storeX = [&](int b) {
        const uint32_t xb = sb + SM_X + (uint32_t)b * 18432;
        #pragma unroll
        for (int q = 0; q < 8; q++) {
            const int tok = lt + 16 * q;
            sts128(xb + (uint32_t)(tok * 144 + 16 * lf), xr[q]);
        }
    };
    auto issueW = [&](int c) {
        if (c >= NCHUNK) return;
        const char* gs = (const char*)(g_wfrag + (size_t)c * 1024);
        const uint32_t dst = sb + SM_W + (uint32_t)(c & 1) * 4096 + tid * 32;
        cpa16(dst,      gs + tid * 32);
        cpa16(dst + 16, gs + tid * 32 + 16);
        CP_COMMIT();
    };

    prefetchX(0);
    issueW(0);

    const int fr = lane >> 2;     // fragment row within m16
    const int fc = lane & 3;      // fragment col group

    for (int c = 0; c < NCHUNK; c++) {
        const int b = c & 1;
        __syncthreads();                 // compute(c-1) done: buffers reusable
        storeX(b);
        if (c + 1 < NCHUNK) {
            prefetchX(c + 1);
            issueW(c + 1);
            CP_WAIT1();                  // W(c) landed
        } else {
            CP_WAIT0();
        }
        __syncthreads();                 // X(c) stores + W(c) visible

        const uint32_t xbase = sb + SM_X + (uint32_t)b * 18432;
        const uint32_t wbase = sb + SM_W + (uint32_t)b * 4096;

        #pragma unroll
        for (int ks = 0; ks < 2; ks++) {
            // B fragments (conflict-free LDS.64, per-lane fragment order)
            uint32_t bh[4][2], bl[4][2];
            #pragma unroll
            for (int nt = 0; nt < 4; nt++) {
                lds64u(wbase + (uint32_t)(((0 * 2 + ks) * 4 + nt) * 256 + 8 * lane),
                       bh[nt][0], bh[nt][1]);
                lds64u(wbase + (uint32_t)(((1 * 2 + ks) * 4 + nt) * 256 + 8 * lane),
                       bl[nt][0], bl[nt][1]);
            }
            const int k0 = ks * 16 + 2 * fc;
            #pragma unroll
            for (int mt = 0; mt < 2; mt++) {
                const int tok0 = 32 * wid + 16 * mt + fr;
                float x00, x01, x10, x11, x20, x21, x30, x31;
                lds64f(xbase + (uint32_t)((tok0 * 36 + k0) * 4),           x00, x01);
                lds64f(xbase + (uint32_t)(((tok0 + 8) * 36 + k0) * 4),     x10, x11);
                lds64f(xbase + (uint32_t)((tok0 * 36 + k0 + 8) * 4),       x20, x21);
                lds64f(xbase + (uint32_t)(((tok0 + 8) * 36 + k0 + 8) * 4), x30, x31);
                uint32_t ah[4], al[4];
                ah[0] = prmt_hi(x00, x01);
                ah[1] = prmt_hi(x10, x11);
                ah[2] = prmt_hi(x20, x21);
                ah[3] = prmt_hi(x30, x31);
                al[0] = cvt_bf16x2(x00 - trunc_bf(x00), x01 - trunc_bf(x01));
                al[1] = cvt_bf16x2(x10 - trunc_bf(x10), x11 - trunc_bf(x11));
                al[2] = cvt_bf16x2(x20 - trunc_bf(x20), x21 - trunc_bf(x21));
                al[3] = cvt_bf16x2(x30 - trunc_bf(x30), x31 - trunc_bf(x31));
                #pragma unroll
                for (int nt = 0; nt < 4; nt++) {
                    mma16816(d[mt][nt], ah, bh[nt]);
                    mma16816(d[mt][nt], al, bh[nt]);
                    mma16816(d[mt][nt], ah, bl[nt]);
                }
            }
        }
    }

    // ---------------- write D fragments to smem [128][33] ----------------
    __syncthreads();
    float* red = Xsf;
    #pragma unroll
    for (int mt = 0; mt < 2; mt++) {
        const int tok = 32 * wid + 16 * mt + fr;
        #pragma unroll
        for (int nt = 0; nt < 4; nt++) {
            const int n = 8 * nt + 2 * fc;
            red[tok * 33 + n]           = d[mt][nt][0];
            red[tok * 33 + n + 1]       = d[mt][nt][1];
            red[(tok + 8) * 33 + n]     = d[mt][nt][2];
            red[(tok + 8) * 33 + n + 1] = d[mt][nt][3];
        }
    }
    __syncthreads();

    // ---------------- per-token epilogue (128 threads, 1 token each) ----------------
    {
        const int t = tb + tid;
        float nz[16];
        {
            float4 ev[4];
            const float4* ep = reinterpret_cast<const float4*>(eps + (size_t)t * 16);
            ev[0] = ep[0]; ev[1] = ep[1]; ev[2] = ep[2]; ev[3] = ep[3];
            const float* ef = reinterpret_cast<const float*>(ev);
            #pragma unroll
            for (int e = 0; e < 16; e++) {
                float2 bso = g_bias[e];
                float route = red[tid * 33 + e] + bso.x;
                float noise = red[tid * 33 + 16 + e] + bso.y;
                nz[e] = route + ef[e] * softplus_f(noise);
            }
        }

        float m = nz[0];
        #pragma unroll
        for (int e = 1; e < 16; e++) m = fmaxf(m, nz[e]);
        float ex[16], ssum = 0.f;
        #pragma unroll
        for (int e = 0; e < 16; e++) { ex[e] = expf(nz[e] - m); ssum += ex[e]; }
        float inv = 1.f / ssum;

        int i1 = 0; float v1 = nz[0];
        #pragma unroll
        for (int e = 1; e < 16; e++) if (nz[e] > v1) { v1 = nz[e]; i1 = e; }
        int i2 = -1; float v2 = -INFINITY;
        #pragma unroll
        for (int e = 0; e < 16; e++) if (e != i1 && nz[e] > v2) { v2 = nz[e]; i2 = e; }

        float t2 = expf(v2 - v1);
        float r1 = 1.f / (1.f + t2);
        float r2 = t2 * r1;

        {
            float ro[16];
            #pragma unroll
            for (int e = 0; e < 16; e++)
                ro[e] = (e == i1) ? r1 : ((e == i2) ? r2 : 0.f);
            float4* op = reinterpret_cast<float4*>(out + (size_t)t * 16);
            op[0] = make_float4(ro[0],  ro[1],  ro[2],  ro[3]);
            op[1] = make_float4(ro[4],  ro[5],  ro[6],  ro[7]);
            op[2] = make_float4(ro[8],  ro[9],  ro[10], ro[11]);
            op[3] = make_float4(ro[12], ro[13], ro[14], ro[15]);
        }
        if (out_size >= IDX_OFF + NTOK * 2) {
            float2* ip = reinterpret_cast<float2*>(out + IDX_OFF + (size_t)t * 2);
            ip[0] = make_float2((float)i1, (float)i2);
        }
        if (out_size >= G1_OFF + NTOK * NEXP) {
            float g[16];
            #pragma unroll
            for (int e = 0; e < 16; e++) g[e] = ex[e] * inv;
            float4* gp = reinterpret_cast<float4*>(out + G1_OFF + (size_t)t * 16);
            gp[0] = make_float4(g[0],  g[1],  g[2],  g[3]);
            gp[1] = make_float4(g[4],  g[5],  g[6],  g[7]);
            gp[2] = make_float4(g[8],  g[9],  g[10], g[11]);
            gp[3] = make_float4(g[12], g[13], g[14], g[15]);
        }
    }
}

// ---------------- launch ----------------
extern "C" void kernel_launch(void* const* d_in, const int* in_sizes, int n_in,
                              void* d_out, int out_size)
{
    const float* mh      = (const float*)d_in[0];
    const float* dt      = (const float*)d_in[1];
    const float* dd      = (const float*)d_in[2];
    const float* drg     = (const float*)d_in[3];
    const float* dent    = (const float*)d_in[4];
    const float* city    = (const float*)d_in[5];
    const float* w_route = (const float*)d_in[6];
    const float* b_route = (const float*)d_in[7];
    const float* w_noise = (const float*)d_in[8];
    const float* b_noise = (const float*)d_in[9];
    const float* eps     = (const float*)d_in[10];
    const int*   ci      = (const int*)d_in[11];

    cudaFuncSetAttribute(router_main,
                         cudaFuncAttributeMaxDynamicSharedMemorySize, SMEM_BYTES);

    prep_kernel<<<(NCHUNK * 1024 + 255) / 256, 256>>>(w_route, b_route,
                                                      w_noise, b_noise, city, ci);
    router_main<<<NBLK, TPB, SMEM_BYTES>>>(mh, dt, dd, drg, dent, eps,
                                           (float*)d_out, out_size);
}